// round 3
// baseline (speedup 1.0000x reference)
#include <cuda_runtime.h>

// DAM softmax loss:
//   logits = S * costh, except target col: S * (cos_t - MARGIN*exp(1-cos_t)/LAMDA)
//   loss = mean_row( logsumexp(logits_row) - logits_row[target] )
// Since costh in [0,1), S*costh < 15 -> use fixed max = 15 (no max pass).
// One block per row, single pass, ex2-based exp, target handled as a scalar
// correction by thread 0 (its reload is an L2/L1 hit).
// NOTE: harness narrows int64 labels to int32 -> read as const int*.

static constexpr int   B_ROWS  = 8192;
static constexpr int   C_COLS  = 10000;
static constexpr int   THREADS = 256;
static constexpr float S_SCALE = 15.0f;
static constexpr float MARGIN_OVER_LAMDA = 0.3f / 2.0f;  // 0.15

__device__ double g_acc;

__global__ void zero_acc_kernel() { g_acc = 0.0; }

__device__ __forceinline__ float ex2_approx(float x) {
    float r;
    asm("ex2.approx.f32 %0, %1;" : "=f"(r) : "f"(x));
    return r;
}

__global__ void __launch_bounds__(THREADS)
dam_row_loss_kernel(const float* __restrict__ costh,
                    const int* __restrict__ label) {
    const int row = blockIdx.x;
    const float4* __restrict__ rp =
        reinterpret_cast<const float4*>(costh + (size_t)row * C_COLS);

    // exp(S*c - 15) = exp2( (S*log2e)*c - 15*log2e )
    const float L2E  = 1.4426950408889634f;
    const float SL2E = S_SCALE * L2E;
    const float BIAS = -S_SCALE * L2E;

    float s = 0.0f;
    const int nvec = C_COLS / 4;  // 2500; row stride 40000 B is 16B-aligned
    #pragma unroll 2
    for (int i = threadIdx.x; i < nvec; i += THREADS) {
        float4 v = rp[i];
        s += ex2_approx(fmaf(v.x, SL2E, BIAS));
        s += ex2_approx(fmaf(v.y, SL2E, BIAS));
        s += ex2_approx(fmaf(v.z, SL2E, BIAS));
        s += ex2_approx(fmaf(v.w, SL2E, BIAS));
    }

    // warp reduce
    #pragma unroll
    for (int off = 16; off; off >>= 1)
        s += __shfl_xor_sync(0xffffffffu, s, off);

    __shared__ float warp_sums[THREADS / 32];
    if ((threadIdx.x & 31) == 0) warp_sums[threadIdx.x >> 5] = s;
    __syncthreads();

    if (threadIdx.x == 0) {
        float tot = 0.0f;
        #pragma unroll
        for (int w = 0; w < THREADS / 32; w++) tot += warp_sums[w];

        int t = label[row];
        t = min(max(t, 0), C_COLS - 1);  // defensive clamp (avoid OOB on dtype surprise)
        const float ct    = costh[(size_t)row * C_COLS + t];
        const float delta = MARGIN_OVER_LAMDA * expf(1.0f - ct);
        const float ct2   = ct - delta;  // margin-adjusted target cosine

        // replace target term: remove exp(S*ct-15), add exp(S*ct2-15)
        tot += expf(fmaf(S_SCALE, ct2, -S_SCALE)) -
               expf(fmaf(S_SCALE, ct,  -S_SCALE));

        // lse = 15 + log(tot); loss_row = lse - S*ct2
        const float loss_row = 15.0f + logf(tot) - S_SCALE * ct2;
        atomicAdd(&g_acc, (double)loss_row);
    }
}

__global__ void finalize_kernel(float* __restrict__ out) {
    out[0] = (float)(g_acc * (1.0 / (double)B_ROWS));
}

extern "C" void kernel_launch(void* const* d_in, const int* in_sizes, int n_in,
                              void* d_out, int out_size) {
    const float* costh = (const float*)d_in[0];
    const int*   label = (const int*)d_in[1];
    float*       out   = (float*)d_out;

    zero_acc_kernel<<<1, 1>>>();
    dam_row_loss_kernel<<<B_ROWS, THREADS>>>(costh, label);
    finalize_kernel<<<1, 1>>>(out);
}

// round 4
// speedup vs baseline: 1.0046x; 1.0046x over previous
#include <cuda_runtime.h>

// DAM softmax loss, single fused kernel.
//   logits = S * costh, except target col: S * (cos_t - MARGIN*exp(1-cos_t)/LAMDA)
//   loss = mean_row( logsumexp(logits_row) - logits_row[target] )
// costh in [0,1) -> S*costh < 15 -> fixed max = 15, single pass, no max scan.
// One block per row; cross-row reduction via atomicAdd(double) + last-block
// ticket. Last block writes out and RESETS the globals so every graph replay
// starts from identical state (deterministic, capture-safe, no allocs).

static constexpr int   B_ROWS  = 8192;
static constexpr int   C_COLS  = 10000;
static constexpr int   THREADS = 256;
static constexpr float S_SCALE = 15.0f;
static constexpr float MARGIN_OVER_LAMDA = 0.3f / 2.0f;  // 0.15

__device__ double       g_acc  = 0.0;  // zero-init at module load
__device__ unsigned int g_done = 0u;

__device__ __forceinline__ float ex2_approx(float x) {
    float r;
    asm("ex2.approx.f32 %0, %1;" : "=f"(r) : "f"(x));
    return r;
}

__global__ void __launch_bounds__(THREADS)
dam_loss_fused_kernel(const float* __restrict__ costh,
                      const int* __restrict__ label,
                      float* __restrict__ out) {
    const int row = blockIdx.x;
    const float4* __restrict__ rp =
        reinterpret_cast<const float4*>(costh + (size_t)row * C_COLS);

    // exp(S*c - 15) = exp2( (S*log2e)*c - 15*log2e )
    const float L2E  = 1.4426950408889634f;
    const float SL2E = S_SCALE * L2E;
    const float BIAS = -S_SCALE * L2E;

    const int nvec = C_COLS / 4;            // 2500; rows are 16B-aligned (40000 B)
    float s = 0.0f;

    // Main body: batches of 4 float4 loads (MLP=4 per thread) then the math.
    int i = threadIdx.x;
    #pragma unroll 1
    for (; i + 3 * THREADS < nvec; i += 4 * THREADS) {
        float4 v0 = rp[i];
        float4 v1 = rp[i + THREADS];
        float4 v2 = rp[i + 2 * THREADS];
        float4 v3 = rp[i + 3 * THREADS];
        s += ex2_approx(fmaf(v0.x, SL2E, BIAS));
        s += ex2_approx(fmaf(v0.y, SL2E, BIAS));
        s += ex2_approx(fmaf(v0.z, SL2E, BIAS));
        s += ex2_approx(fmaf(v0.w, SL2E, BIAS));
        s += ex2_approx(fmaf(v1.x, SL2E, BIAS));
        s += ex2_approx(fmaf(v1.y, SL2E, BIAS));
        s += ex2_approx(fmaf(v1.z, SL2E, BIAS));
        s += ex2_approx(fmaf(v1.w, SL2E, BIAS));
        s += ex2_approx(fmaf(v2.x, SL2E, BIAS));
        s += ex2_approx(fmaf(v2.y, SL2E, BIAS));
        s += ex2_approx(fmaf(v2.z, SL2E, BIAS));
        s += ex2_approx(fmaf(v2.w, SL2E, BIAS));
        s += ex2_approx(fmaf(v3.x, SL2E, BIAS));
        s += ex2_approx(fmaf(v3.y, SL2E, BIAS));
        s += ex2_approx(fmaf(v3.z, SL2E, BIAS));
        s += ex2_approx(fmaf(v3.w, SL2E, BIAS));
    }
    // Tail (nvec=2500 -> last partial batch)
    for (; i < nvec; i += THREADS) {
        float4 v = rp[i];
        s += ex2_approx(fmaf(v.x, SL2E, BIAS));
        s += ex2_approx(fmaf(v.y, SL2E, BIAS));
        s += ex2_approx(fmaf(v.z, SL2E, BIAS));
        s += ex2_approx(fmaf(v.w, SL2E, BIAS));
    }

    // warp reduce
    #pragma unroll
    for (int off = 16; off; off >>= 1)
        s += __shfl_xor_sync(0xffffffffu, s, off);

    __shared__ float warp_sums[THREADS / 32];
    if ((threadIdx.x & 31) == 0) warp_sums[threadIdx.x >> 5] = s;
    __syncthreads();

    if (threadIdx.x == 0) {
        float tot = 0.0f;
        #pragma unroll
        for (int w = 0; w < THREADS / 32; w++) tot += warp_sums[w];

        int t = label[row];
        t = min(max(t, 0), C_COLS - 1);
        const float ct    = costh[(size_t)row * C_COLS + t];  // L1/L2 hit
        const float delta = MARGIN_OVER_LAMDA * expf(1.0f - ct);
        const float ct2   = ct - delta;  // margin-adjusted target cosine

        // replace target term: remove exp(S*ct-15), add exp(S*ct2-15)
        tot += expf(fmaf(S_SCALE, ct2, -S_SCALE)) -
               expf(fmaf(S_SCALE, ct,  -S_SCALE));

        // lse = 15 + log(tot); loss_row = lse - S*ct2
        const float loss_row = 15.0f + logf(tot) - S_SCALE * ct2;
        atomicAdd(&g_acc, (double)loss_row);

        // last-block-done: finalize + reset globals for the next graph replay
        __threadfence();
        const unsigned ticket = atomicAdd(&g_done, 1u);
        if (ticket == (unsigned)(gridDim.x - 1)) {
            out[0] = (float)(g_acc * (1.0 / (double)B_ROWS));
            g_acc  = 0.0;
            g_done = 0u;
            __threadfence();
        }
    }
}

extern "C" void kernel_launch(void* const* d_in, const int* in_sizes, int n_in,
                              void* d_out, int out_size) {
    const float* costh = (const float*)d_in[0];
    const int*   label = (const int*)d_in[1];
    float*       out   = (float*)d_out;

    dam_loss_fused_kernel<<<B_ROWS, THREADS>>>(costh, label, out);
}

// round 5
// speedup vs baseline: 1.0052x; 1.0006x over previous
#include <cuda_runtime.h>

// DAM softmax loss, single fused PERSISTENT kernel.
//   logits = S * costh, except target col: S * (cos_t - MARGIN*exp(1-cos_t)/LAMDA)
//   loss = mean_row( logsumexp(logits_row) - logits_row[target] )
// costh in [0,1) -> S*costh < 15 -> fixed max = 15, single pass, no max scan.
// Exactly one wave of CTAs (148 SM x 8 blocks) grid-strides over rows: no wave
// transitions, balanced finish. Streaming loads (__ldcs) since data is
// read-once. Cross-row reduction via atomicAdd(double); last-block ticket
// finalizes and resets globals (deterministic across graph replays).

static constexpr int   B_ROWS  = 8192;
static constexpr int   C_COLS  = 10000;
static constexpr int   THREADS = 256;
static constexpr int   NUM_SMS = 148;
static constexpr int   BLOCKS_PER_SM = 8;       // 8 * 256 = 2048 threads/SM
static constexpr int   GRID    = NUM_SMS * BLOCKS_PER_SM;  // 1184, one wave
static constexpr float S_SCALE = 15.0f;
static constexpr float MARGIN_OVER_LAMDA = 0.3f / 2.0f;    // 0.15

__device__ double       g_acc  = 0.0;
__device__ unsigned int g_done = 0u;

__device__ __forceinline__ float ex2_approx(float x) {
    float r;
    asm("ex2.approx.f32 %0, %1;" : "=f"(r) : "f"(x));
    return r;
}

__global__ void __launch_bounds__(THREADS, BLOCKS_PER_SM)
dam_loss_persistent_kernel(const float* __restrict__ costh,
                           const int* __restrict__ label,
                           float* __restrict__ out) {
    // exp(S*c - 15) = exp2( (S*log2e)*c - 15*log2e )
    const float L2E  = 1.4426950408889634f;
    const float SL2E = S_SCALE * L2E;
    const float BIAS = -S_SCALE * L2E;
    const int   nvec = C_COLS / 4;  // 2500; rows are 16B-aligned (40000 B)

    __shared__ float warp_sums[THREADS / 32];

    for (int row = blockIdx.x; row < B_ROWS; row += GRID) {
        const float4* __restrict__ rp =
            reinterpret_cast<const float4*>(costh + (size_t)row * C_COLS);

        float s0 = 0.0f, s1 = 0.0f, s2 = 0.0f, s3 = 0.0f;

        int i = threadIdx.x;
        #pragma unroll 1
        for (; i + 3 * THREADS < nvec; i += 4 * THREADS) {
            float4 v0 = __ldcs(&rp[i]);
            float4 v1 = __ldcs(&rp[i + THREADS]);
            float4 v2 = __ldcs(&rp[i + 2 * THREADS]);
            float4 v3 = __ldcs(&rp[i + 3 * THREADS]);
            s0 += ex2_approx(fmaf(v0.x, SL2E, BIAS));
            s1 += ex2_approx(fmaf(v0.y, SL2E, BIAS));
            s2 += ex2_approx(fmaf(v0.z, SL2E, BIAS));
            s3 += ex2_approx(fmaf(v0.w, SL2E, BIAS));
            s0 += ex2_approx(fmaf(v1.x, SL2E, BIAS));
            s1 += ex2_approx(fmaf(v1.y, SL2E, BIAS));
            s2 += ex2_approx(fmaf(v1.z, SL2E, BIAS));
            s3 += ex2_approx(fmaf(v1.w, SL2E, BIAS));
            s0 += ex2_approx(fmaf(v2.x, SL2E, BIAS));
            s1 += ex2_approx(fmaf(v2.y, SL2E, BIAS));
            s2 += ex2_approx(fmaf(v2.z, SL2E, BIAS));
            s3 += ex2_approx(fmaf(v2.w, SL2E, BIAS));
            s0 += ex2_approx(fmaf(v3.x, SL2E, BIAS));
            s1 += ex2_approx(fmaf(v3.y, SL2E, BIAS));
            s2 += ex2_approx(fmaf(v3.z, SL2E, BIAS));
            s3 += ex2_approx(fmaf(v3.w, SL2E, BIAS));
        }
        for (; i < nvec; i += THREADS) {
            float4 v = __ldcs(&rp[i]);
            s0 += ex2_approx(fmaf(v.x, SL2E, BIAS));
            s1 += ex2_approx(fmaf(v.y, SL2E, BIAS));
            s2 += ex2_approx(fmaf(v.z, SL2E, BIAS));
            s3 += ex2_approx(fmaf(v.w, SL2E, BIAS));
        }

        float s = (s0 + s1) + (s2 + s3);
        #pragma unroll
        for (int off = 16; off; off >>= 1)
            s += __shfl_xor_sync(0xffffffffu, s, off);

        if ((threadIdx.x & 31) == 0) warp_sums[threadIdx.x >> 5] = s;
        __syncthreads();

        if (threadIdx.x == 0) {
            float tot = 0.0f;
            #pragma unroll
            for (int w = 0; w < THREADS / 32; w++) tot += warp_sums[w];

            int t = label[row];
            t = min(max(t, 0), C_COLS - 1);
            const float ct    = __ldg(&costh[(size_t)row * C_COLS + t]);
            const float delta = MARGIN_OVER_LAMDA * expf(1.0f - ct);
            const float ct2   = ct - delta;  // margin-adjusted target cosine

            // replace target term: remove exp(S*ct-15), add exp(S*ct2-15)
            tot += expf(fmaf(S_SCALE, ct2, -S_SCALE)) -
                   expf(fmaf(S_SCALE, ct,  -S_SCALE));

            // lse = 15 + log(tot); loss_row = lse - S*ct2
            const float loss_row = 15.0f + logf(tot) - S_SCALE * ct2;
            atomicAdd(&g_acc, (double)loss_row);
        }
        __syncthreads();  // warp_sums reuse across row iterations
    }

    // Block done: last of GRID blocks finalizes + resets for next replay.
    if (threadIdx.x == 0) {
        __threadfence();
        const unsigned ticket = atomicAdd(&g_done, 1u);
        if (ticket == (unsigned)(GRID - 1)) {
            out[0] = (float)(g_acc * (1.0 / (double)B_ROWS));
            g_acc  = 0.0;
            g_done = 0u;
            __threadfence();
        }
    }
}

extern "C" void kernel_launch(void* const* d_in, const int* in_sizes, int n_in,
                              void* d_out, int out_size) {
    const float* costh = (const float*)d_in[0];
    const int*   label = (const int*)d_in[1];
    float*       out   = (float*)d_out;

    dam_loss_persistent_kernel<<<GRID, THREADS>>>(costh, label, out);
}